// round 13
// baseline (speedup 1.0000x reference)
#include <cuda_runtime.h>
#include <cstdint>
#include <cstddef>

#define IMG 256
#define HW  65536
#define NF  64
#define NB  8
#define NL  15
#define CH  8

typedef unsigned long long ull;

// ---------------- scratch (device globals; no allocation allowed) ----------------
__device__ float g_xpre[(size_t)NB * HW];                  // 2 MB
__device__ float g_h0[(size_t)NB * NF * HW];               // 128 MB
__device__ float g_h1[(size_t)NB * NF * HW];               // 128 MB
__device__ float g_part[NF * 2 * 2048];                    // per-block stats partials, 1 MB
__device__ float g_scale[NL * NF];
__device__ float g_shift[NL * NF];
// weights pre-paired: g_wp[(((l*8+chunk)*CH+icl)*32+pg)*10+k] = (w[oc=2pg], w[oc=2pg+1]) at tap k
__device__ ull   g_wp[(size_t)NL * 8 * CH * 32 * 10];      // ~2.46 MB

// ---------------- f32x2 helpers (per-lane exact IEEE fp32) -------------------------
__device__ __forceinline__ ull pack2(float v) {
    ull r; asm("mov.b64 %0, {%1, %1};" : "=l"(r) : "f"(v)); return r;
}
__device__ __forceinline__ ull mul2(ull a, ull b) {
    ull d; asm("mul.rn.f32x2 %0, %1, %2;" : "=l"(d) : "l"(a), "l"(b)); return d;
}
__device__ __forceinline__ void fma2(ull& d, ull a, ull b) {
    asm("fma.rn.f32x2 %0, %1, %2, %0;" : "+l"(d) : "l"(a), "l"(b));
}
__device__ __forceinline__ ull add2(ull a, ull b) {
    ull d; asm("add.rn.f32x2 %0, %1, %2;" : "=l"(d) : "l"(a), "l"(b)); return d;
}
__device__ __forceinline__ float2 unpack2(ull v) {
    float2 r; asm("mov.b64 {%0, %1}, %2;" : "=f"(r.x), "=f"(r.y) : "l"(v)); return r;
}

// ---------------- weight pre-pairing ------------------------------------------------
__global__ void wprep_k(const float* __restrict__ w) {
    int i = blockIdx.x * blockDim.x + threadIdx.x;
    if (i >= NL * 8 * CH * 32 * 10) return;
    int k   = i % 10;
    int r   = i / 10;
    int pg  = r % 32;
    int r2  = r / 32;
    int icl = r2 % CH;
    int r3  = r2 / CH;
    int chunk = r3 % 8;
    int l     = r3 / 8;
    int ic = chunk * CH + icl;
    unsigned lo = 0, hi = 0;
    if (k < 9) {
        lo = __float_as_uint(w[(((size_t)l * NF + 2 * pg)     * NF + ic) * 9 + k]);
        hi = __float_as_uint(w[(((size_t)l * NF + 2 * pg + 1) * NF + ic) * 9 + k]);
    }
    g_wp[i] = ((ull)hi << 32) | (ull)lo;
}

// ---------------- preprocessing (R1/R9 source, verbatim) ---------------------------
__global__ __launch_bounds__(256) void preprocess_k(const float* __restrict__ x) {
    __shared__ float t[20][20];
    int tx = threadIdx.x & 15, ty = threadIdx.x >> 4;
    int x0 = blockIdx.x * 16, y0 = blockIdx.y * 16, b = blockIdx.z;
    const float* xb = x + (size_t)b * HW;
    for (int i = threadIdx.x; i < 400; i += 256) {
        int yy = i / 20, xx = i % 20;
        int gy = y0 + yy - 2, gx = x0 + xx - 2;
        if (gy < 0) gy = -gy;
        if (gy > 255) gy = 510 - gy;
        if (gx < 0) gx = -gx;
        if (gx > 255) gx = 510 - gx;
        float v = xb[gy * IMG + gx];
        float xn = (v + 1.f) * 0.5f;
        xn = fminf(fmaxf(xn, 1e-6f), 1.f);
        t[yy][xx] = 0.6f * xn + 0.4f * xn * sqrtf(xn);
    }
    __syncthreads();
    float c = t[ty + 2][tx + 2];
    float num = 0.f, den = 0.f;
#pragma unroll
    for (int dy = -2; dy <= 2; dy++)
#pragma unroll
        for (int dx = -2; dx <= 2; dx++) {
            float nb = t[ty + 2 + dy][tx + 2 + dx];
            float d = nb - c;
            float w = expf(-(float)(dy * dy + dx * dx) * 2.0e-4f - d * d * 200.f);
            num += w * nb;
            den += w;
        }
    g_xpre[(size_t)b * HW + (size_t)(y0 + ty) * IMG + (x0 + tx)] = num / den;
}

// ---------------- init conv (R1/R9 source, verbatim) -------------------------------
__global__ __launch_bounds__(256) void conv_init_k(const float* __restrict__ w) {
    __shared__ float in_s[18][18];
    __shared__ __align__(16) float w_s[NF * 12];
    int tx = threadIdx.x & 15, ty = threadIdx.x >> 4;
    int x0 = blockIdx.x * 16, y0 = blockIdx.y * 16, b = blockIdx.z;
    for (int i = threadIdx.x; i < 324; i += 256) {
        int yy = i / 18, xx = i % 18;
        int gy = y0 + yy - 1, gx = x0 + xx - 1;
        float v = 0.f;
        if (gy >= 0 && gy < 256 && gx >= 0 && gx < 256)
            v = g_xpre[(size_t)b * HW + (size_t)gy * IMG + gx];
        in_s[yy][xx] = v;
    }
    for (int i = threadIdx.x; i < NF * 9; i += 256)
        w_s[(i / 9) * 12 + (i % 9)] = w[i];
    __syncthreads();
    float i00 = in_s[ty][tx],     i01 = in_s[ty][tx + 1],     i02 = in_s[ty][tx + 2];
    float i10 = in_s[ty + 1][tx], i11 = in_s[ty + 1][tx + 1], i12 = in_s[ty + 1][tx + 2];
    float i20 = in_s[ty + 2][tx], i21 = in_s[ty + 2][tx + 1], i22 = in_s[ty + 2][tx + 2];
    float* outp = g_h0 + (size_t)b * NF * HW + (size_t)(y0 + ty) * IMG + (x0 + tx);
#pragma unroll
    for (int oc = 0; oc < NF; oc++) {
        float4 wa = *(const float4*)&w_s[oc * 12];
        float4 wb = *(const float4*)&w_s[oc * 12 + 4];
        float  wc = w_s[oc * 12 + 8];
        float a = i00 * wa.x + i01 * wa.y + i02 * wa.z + i10 * wa.w +
                  i11 * wb.x + i12 * wb.y + i20 * wb.z + i21 * wb.w + i22 * wc;
        outp[(size_t)oc * HW] = fmaxf(a, 0.f);
    }
}

// ---------------- body conv: f32x2 (R10), stats -> deterministic partials ----------
__global__ __launch_bounds__(256) void conv_body_k(int l) {
    __shared__ float in_s[CH][18][20];
    __shared__ __align__(16) ull w_s2[CH * 32 * 10];       // [icl][pg][k] pairs, 20 KB
    __shared__ float red_s[2][NF][8];
    __shared__ float val_s[16][16];

    const float* in  = (l & 1) ? g_h1 : g_h0;
    float*       out = (l & 1) ? g_h0 : g_h1;
    const float* sc = (l > 0) ? &g_scale[(l - 1) * NF] : nullptr;
    const float* sh = (l > 0) ? &g_shift[(l - 1) * NF] : nullptr;

    int tid = threadIdx.x;
    int ocg = tid >> 6, pid = tid & 63;
    int row = pid >> 2, cg = pid & 3;
    int x0 = blockIdx.x * 16, y0 = blockIdx.y * 16, b = blockIdx.z;
    int bid = (b * 16 + blockIdx.y) * 16 + blockIdx.x;     // 0..2047, fixed mapping
    const float* inb = in + (size_t)b * NF * HW;

    ull acc[4][8];
#pragma unroll
    for (int px = 0; px < 4; px++)
#pragma unroll
        for (int p = 0; p < 8; p++) acc[px][p] = 0ull;

    for (int c0 = 0; c0 < NF; c0 += CH) {
        // stage input tile: R9's BN-apply source (same values)
        for (int i = tid; i < CH * 324; i += 256) {
            int c = i / 324, r2 = i % 324, yy = r2 / 18, xx = r2 % 18;
            int gy = y0 + yy - 1, gx = x0 + xx - 1;
            float v = 0.f;
            if (gy >= 0 && gy < 256 && gx >= 0 && gx < 256) {
                v = inb[(size_t)(c0 + c) * HW + (size_t)gy * IMG + gx];
                if (sc) v = fmaxf(v * sc[c0 + c] + sh[c0 + c], 0.f);
            }
            in_s[c][yy][xx] = v;
        }
        // stage paired weights (coalesced 8B copies)
        {
            const ull* src = g_wp + ((size_t)l * 8 + (c0 >> 3)) * (CH * 32 * 10);
            for (int i = tid; i < CH * 32 * 10; i += 256) w_s2[i] = src[i];
        }
        __syncthreads();
#pragma unroll 1
        for (int icl = 0; icl < CH; icl++) {
            const float* p = &in_s[icl][row][cg * 4];
            float4 a0 = *(const float4*)p;        float2 b0 = *(const float2*)(p + 4);
            float4 a1 = *(const float4*)(p + 20); float2 b1 = *(const float2*)(p + 24);
            float4 a2 = *(const float4*)(p + 40); float2 b2 = *(const float2*)(p + 44);
            ull d0[6] = {pack2(a0.x), pack2(a0.y), pack2(a0.z), pack2(a0.w), pack2(b0.x), pack2(b0.y)};
            ull d1[6] = {pack2(a1.x), pack2(a1.y), pack2(a1.z), pack2(a1.w), pack2(b1.x), pack2(b1.y)};
            ull d2[6] = {pack2(a2.x), pack2(a2.y), pack2(a2.z), pack2(a2.w), pack2(b2.x), pack2(b2.y)};
#pragma unroll
            for (int pr = 0; pr < 8; pr++) {
                int pg = ocg * 8 + pr;                      // oc pair (2pg, 2pg+1)
                const ull* wp = &w_s2[(icl * 32 + pg) * 10];
                ulonglong2 w01 = *(const ulonglong2*)(wp);
                ulonglong2 w23 = *(const ulonglong2*)(wp + 2);
                ulonglong2 w45 = *(const ulonglong2*)(wp + 4);
                ulonglong2 w67 = *(const ulonglong2*)(wp + 6);
                ull w8 = wp[8];
#pragma unroll
                for (int px = 0; px < 4; px++) {
                    ull t = mul2(d0[px], w01.x);
                    fma2(t, d0[px + 1], w01.y);
                    fma2(t, d0[px + 2], w23.x);
                    fma2(t, d1[px],     w23.y);
                    fma2(t, d1[px + 1], w45.x);
                    fma2(t, d1[px + 2], w45.y);
                    fma2(t, d2[px],     w67.x);
                    fma2(t, d2[px + 1], w67.y);
                    fma2(t, d2[px + 2], w8);
                    acc[px][pr] = add2(acc[px][pr], t);
                }
            }
        }
        __syncthreads();
    }

    // epilogue 1: unpack, ReLU + store
    float pr[4][16];
    size_t pbase = (size_t)b * NF * HW + (size_t)(y0 + row) * IMG + (x0 + cg * 4);
#pragma unroll
    for (int pp = 0; pp < 8; pp++) {
#pragma unroll
        for (int px = 0; px < 4; px++) {
            float2 u = unpack2(acc[px][pp]);
            pr[px][2 * pp]     = fmaxf(u.x, 0.f);
            pr[px][2 * pp + 1] = fmaxf(u.y, 0.f);
        }
    }
#pragma unroll
    for (int j = 0; j < 16; j++) {
        int oc = ocg * 16 + j;
        *(float4*)(out + pbase + (size_t)oc * HW) =
            make_float4(pr[0][j], pr[1][j], pr[2][j], pr[3][j]);
    }

    // epilogue 2: per-block stats partial (identical tree to R10), NO atomics
    int tx = tid & 15, ty = tid >> 4;
    int lane = tid & 31, wid8 = tid >> 5;
    for (int oc = 0; oc < NF; oc++) {
        int og = oc >> 4, j = oc & 15;
        __syncthreads();
        if (ocg == og) {
#pragma unroll
            for (int px = 0; px < 4; px++) val_s[row][cg * 4 + px] = pr[px][j];
        }
        __syncthreads();
        float v = val_s[ty][tx];
        float s = v, q = v * v;
#pragma unroll
        for (int off = 16; off; off >>= 1) {
            s += __shfl_down_sync(0xffffffffu, s, off);
            q += __shfl_down_sync(0xffffffffu, q, off);
        }
        if (lane == 0) { red_s[0][oc][wid8] = s; red_s[1][oc][wid8] = q; }
    }
    __syncthreads();
    if (tid < 128) {
        int oc = tid & 63, which = tid >> 6;
        float t = 0.f;
#pragma unroll
        for (int wd = 0; wd < 8; wd++) t += red_s[which][oc][wd];
        g_part[(oc * 2 + which) * 2048 + bid] = t;          // deterministic store
    }
}

// ---------------- BN finalize: deterministic SEQUENTIAL sum over 2048 partials -----
// One thread per (channel, stat): fixed-order serial fp32 chain, structurally the
// same family as the (passing) atomic-sequential runs, but bit-reproducible.
__global__ __launch_bounds__(128) void bn_finalize_k(const float* __restrict__ gam,
                                                     const float* __restrict__ bet, int l) {
    __shared__ float sum_s[NF], sq_s[NF];
    int tid = threadIdx.x;
    int oc = tid & 63, which = tid >> 6;
    const float* p = &g_part[(oc * 2 + which) * 2048];
    float t = 0.f;
    for (int bid = 0; bid < 2048; bid++) t += p[bid];
    if (which == 0) sum_s[oc] = t; else sq_s[oc] = t;
    __syncthreads();
    if (tid < NF) {
        int c = tid;
        const float n = (float)((size_t)NB * HW);
        float mean = sum_s[c] / n;
        float var = sq_s[c] / n - mean * mean;
        float rs = rsqrtf(var + 1e-5f);
        float scl = gam[c] * rs;
        g_scale[l * NF + c] = scl;
        g_shift[l * NF + c] = bet[c] - mean * scl;
    }
}

// ---------------- final conv (R1/R9 source, verbatim) ------------------------------
__global__ __launch_bounds__(256) void conv_final_k(const float* __restrict__ w, float* __restrict__ outp) {
    __shared__ float in_s[CH][18][18];
    __shared__ __align__(16) float w_s[NF * 12];
    int tx = threadIdx.x & 15, ty = threadIdx.x >> 4;
    int x0 = blockIdx.x * 16, y0 = blockIdx.y * 16, b = blockIdx.z;
    const float* inb = g_h1 + (size_t)b * NF * HW;
    const float* sc = &g_scale[(NL - 1) * NF];
    const float* sh = &g_shift[(NL - 1) * NF];
    for (int i = threadIdx.x; i < NF * 9; i += 256)
        w_s[(i / 9) * 12 + (i % 9)] = w[i];
    float acc = 0.f;
    for (int c0 = 0; c0 < NF; c0 += CH) {
        for (int i = threadIdx.x; i < CH * 324; i += 256) {
            int c = i / 324, r = i % 324, yy = r / 18, xx = r % 18;
            int gy = y0 + yy - 1, gx = x0 + xx - 1;
            float v = 0.f;
            if (gy >= 0 && gy < 256 && gx >= 0 && gx < 256) {
                v = inb[(size_t)(c0 + c) * HW + (size_t)gy * IMG + gx];
                v = fmaxf(v * sc[c0 + c] + sh[c0 + c], 0.f);
            }
            in_s[c][yy][xx] = v;
        }
        __syncthreads();
#pragma unroll
        for (int icl = 0; icl < CH; icl++) {
            float i00 = in_s[icl][ty][tx],     i01 = in_s[icl][ty][tx + 1],     i02 = in_s[icl][ty][tx + 2];
            float i10 = in_s[icl][ty + 1][tx], i11 = in_s[icl][ty + 1][tx + 1], i12 = in_s[icl][ty + 1][tx + 2];
            float i20 = in_s[icl][ty + 2][tx], i21 = in_s[icl][ty + 2][tx + 1], i22 = in_s[icl][ty + 2][tx + 2];
            float4 wa = *(const float4*)&w_s[(c0 + icl) * 12];
            float4 wb = *(const float4*)&w_s[(c0 + icl) * 12 + 4];
            float  wc = w_s[(c0 + icl) * 12 + 8];
            acc += i00 * wa.x + i01 * wa.y + i02 * wa.z + i10 * wa.w +
                   i11 * wb.x + i12 * wb.y + i20 * wb.z + i21 * wb.w + i22 * wc;
        }
        __syncthreads();
    }
    size_t o = (size_t)b * HW + (size_t)(y0 + ty) * IMG + (x0 + tx);
    outp[o] = g_xpre[o] - acc;
}

// ---------------- launch ----------------------------------------------------------
extern "C" void kernel_launch(void* const* d_in, const int* in_sizes, int n_in,
                              void* d_out, int out_size) {
    const float* x       = (const float*)d_in[0];
    const float* w_init  = (const float*)d_in[1];
    const float* w_body  = (const float*)d_in[2];
    const float* bn_g    = (const float*)d_in[3];
    const float* bn_b    = (const float*)d_in[4];
    const float* w_final = (const float*)d_in[5];
    float* out = (float*)d_out;

    dim3 grid(16, 16, NB), blk(256);
    wprep_k<<<(NL * 8 * CH * 32 * 10 + 255) / 256, 256>>>(w_body);
    preprocess_k<<<grid, blk>>>(x);
    conv_init_k<<<grid, blk>>>(w_init);
    for (int l = 0; l < NL; l++) {
        conv_body_k<<<grid, blk>>>(l);
        bn_finalize_k<<<1, 128>>>(bn_g + l * NF, bn_b + l * NF, l);
    }
    conv_final_k<<<grid, blk>>>(w_final, out);
}

// round 14
// speedup vs baseline: 1.0030x; 1.0030x over previous
#include <cuda_runtime.h>
#include <cstdint>
#include <cstddef>

#define IMG 256
#define HW  65536
#define NF  64
#define NB  8
#define NL  15
#define CH  8

typedef unsigned long long ull;

// ---------------- scratch (device globals; no allocation allowed) ----------------
__device__ float g_xpre[(size_t)NB * HW];                  // 2 MB
__device__ float g_h0[(size_t)NB * NF * HW];               // 128 MB
__device__ float g_h1[(size_t)NB * NF * HW];               // 128 MB
__device__ float g_part[NF * 2 * 2048];                    // per-block stats partials, 1 MB
__device__ float g_scale[NL * NF];
__device__ float g_shift[NL * NF];
// weights pre-paired: g_wp[(((l*8+chunk)*CH+icl)*32+pg)*10+k] = (w[oc=2pg], w[oc=2pg+1]) at tap k
__device__ ull   g_wp[(size_t)NL * 8 * CH * 32 * 10];      // ~2.46 MB

// ---------------- f32x2 helpers (per-lane exact IEEE fp32) -------------------------
__device__ __forceinline__ ull pack2(float v) {
    ull r; asm("mov.b64 %0, {%1, %1};" : "=l"(r) : "f"(v)); return r;
}
__device__ __forceinline__ ull mul2(ull a, ull b) {
    ull d; asm("mul.rn.f32x2 %0, %1, %2;" : "=l"(d) : "l"(a), "l"(b)); return d;
}
__device__ __forceinline__ void fma2(ull& d, ull a, ull b) {
    asm("fma.rn.f32x2 %0, %1, %2, %0;" : "+l"(d) : "l"(a), "l"(b));
}
__device__ __forceinline__ ull add2(ull a, ull b) {
    ull d; asm("add.rn.f32x2 %0, %1, %2;" : "=l"(d) : "l"(a), "l"(b)); return d;
}
__device__ __forceinline__ float2 unpack2(ull v) {
    float2 r; asm("mov.b64 {%0, %1}, %2;" : "=f"(r.x), "=f"(r.y) : "l"(v)); return r;
}

// ---------------- weight pre-pairing ------------------------------------------------
__global__ void wprep_k(const float* __restrict__ w) {
    int i = blockIdx.x * blockDim.x + threadIdx.x;
    if (i >= NL * 8 * CH * 32 * 10) return;
    int k   = i % 10;
    int r   = i / 10;
    int pg  = r % 32;
    int r2  = r / 32;
    int icl = r2 % CH;
    int r3  = r2 / CH;
    int chunk = r3 % 8;
    int l     = r3 / 8;
    int ic = chunk * CH + icl;
    unsigned lo = 0, hi = 0;
    if (k < 9) {
        lo = __float_as_uint(w[(((size_t)l * NF + 2 * pg)     * NF + ic) * 9 + k]);
        hi = __float_as_uint(w[(((size_t)l * NF + 2 * pg + 1) * NF + ic) * 9 + k]);
    }
    g_wp[i] = ((ull)hi << 32) | (ull)lo;
}

// ---------------- preprocessing (R1/R9 source, verbatim) ---------------------------
__global__ __launch_bounds__(256) void preprocess_k(const float* __restrict__ x) {
    __shared__ float t[20][20];
    int tx = threadIdx.x & 15, ty = threadIdx.x >> 4;
    int x0 = blockIdx.x * 16, y0 = blockIdx.y * 16, b = blockIdx.z;
    const float* xb = x + (size_t)b * HW;
    for (int i = threadIdx.x; i < 400; i += 256) {
        int yy = i / 20, xx = i % 20;
        int gy = y0 + yy - 2, gx = x0 + xx - 2;
        if (gy < 0) gy = -gy;
        if (gy > 255) gy = 510 - gy;
        if (gx < 0) gx = -gx;
        if (gx > 255) gx = 510 - gx;
        float v = xb[gy * IMG + gx];
        float xn = (v + 1.f) * 0.5f;
        xn = fminf(fmaxf(xn, 1e-6f), 1.f);
        t[yy][xx] = 0.6f * xn + 0.4f * xn * sqrtf(xn);
    }
    __syncthreads();
    float c = t[ty + 2][tx + 2];
    float num = 0.f, den = 0.f;
#pragma unroll
    for (int dy = -2; dy <= 2; dy++)
#pragma unroll
        for (int dx = -2; dx <= 2; dx++) {
            float nb = t[ty + 2 + dy][tx + 2 + dx];
            float d = nb - c;
            float w = expf(-(float)(dy * dy + dx * dx) * 2.0e-4f - d * d * 200.f);
            num += w * nb;
            den += w;
        }
    g_xpre[(size_t)b * HW + (size_t)(y0 + ty) * IMG + (x0 + tx)] = num / den;
}

// ---------------- init conv (R1/R9 source, verbatim) -------------------------------
__global__ __launch_bounds__(256) void conv_init_k(const float* __restrict__ w) {
    __shared__ float in_s[18][18];
    __shared__ __align__(16) float w_s[NF * 12];
    int tx = threadIdx.x & 15, ty = threadIdx.x >> 4;
    int x0 = blockIdx.x * 16, y0 = blockIdx.y * 16, b = blockIdx.z;
    for (int i = threadIdx.x; i < 324; i += 256) {
        int yy = i / 18, xx = i % 18;
        int gy = y0 + yy - 1, gx = x0 + xx - 1;
        float v = 0.f;
        if (gy >= 0 && gy < 256 && gx >= 0 && gx < 256)
            v = g_xpre[(size_t)b * HW + (size_t)gy * IMG + gx];
        in_s[yy][xx] = v;
    }
    for (int i = threadIdx.x; i < NF * 9; i += 256)
        w_s[(i / 9) * 12 + (i % 9)] = w[i];
    __syncthreads();
    float i00 = in_s[ty][tx],     i01 = in_s[ty][tx + 1],     i02 = in_s[ty][tx + 2];
    float i10 = in_s[ty + 1][tx], i11 = in_s[ty + 1][tx + 1], i12 = in_s[ty + 1][tx + 2];
    float i20 = in_s[ty + 2][tx], i21 = in_s[ty + 2][tx + 1], i22 = in_s[ty + 2][tx + 2];
    float* outp = g_h0 + (size_t)b * NF * HW + (size_t)(y0 + ty) * IMG + (x0 + tx);
#pragma unroll
    for (int oc = 0; oc < NF; oc++) {
        float4 wa = *(const float4*)&w_s[oc * 12];
        float4 wb = *(const float4*)&w_s[oc * 12 + 4];
        float  wc = w_s[oc * 12 + 8];
        float a = i00 * wa.x + i01 * wa.y + i02 * wa.z + i10 * wa.w +
                  i11 * wb.x + i12 * wb.y + i20 * wb.z + i21 * wb.w + i22 * wc;
        outp[(size_t)oc * HW] = fmaxf(a, 0.f);
    }
}

// ---------------- body conv: f32x2 (R10), stats -> deterministic partials ----------
__global__ __launch_bounds__(256) void conv_body_k(int l) {
    __shared__ float in_s[CH][18][20];
    __shared__ __align__(16) ull w_s2[CH * 32 * 10];       // [icl][pg][k] pairs, 20 KB
    __shared__ float red_s[2][NF][8];
    __shared__ float val_s[16][16];

    const float* in  = (l & 1) ? g_h1 : g_h0;
    float*       out = (l & 1) ? g_h0 : g_h1;
    const float* sc = (l > 0) ? &g_scale[(l - 1) * NF] : nullptr;
    const float* sh = (l > 0) ? &g_shift[(l - 1) * NF] : nullptr;

    int tid = threadIdx.x;
    int ocg = tid >> 6, pid = tid & 63;
    int row = pid >> 2, cg = pid & 3;
    int x0 = blockIdx.x * 16, y0 = blockIdx.y * 16, b = blockIdx.z;
    int bid = (b * 16 + blockIdx.y) * 16 + blockIdx.x;     // 0..2047, fixed mapping
    const float* inb = in + (size_t)b * NF * HW;

    ull acc[4][8];
#pragma unroll
    for (int px = 0; px < 4; px++)
#pragma unroll
        for (int p = 0; p < 8; p++) acc[px][p] = 0ull;

    for (int c0 = 0; c0 < NF; c0 += CH) {
        // stage input tile: R9's BN-apply source (same values)
        for (int i = tid; i < CH * 324; i += 256) {
            int c = i / 324, r2 = i % 324, yy = r2 / 18, xx = r2 % 18;
            int gy = y0 + yy - 1, gx = x0 + xx - 1;
            float v = 0.f;
            if (gy >= 0 && gy < 256 && gx >= 0 && gx < 256) {
                v = inb[(size_t)(c0 + c) * HW + (size_t)gy * IMG + gx];
                if (sc) v = fmaxf(v * sc[c0 + c] + sh[c0 + c], 0.f);
            }
            in_s[c][yy][xx] = v;
        }
        // stage paired weights (coalesced 8B copies)
        {
            const ull* src = g_wp + ((size_t)l * 8 + (c0 >> 3)) * (CH * 32 * 10);
            for (int i = tid; i < CH * 32 * 10; i += 256) w_s2[i] = src[i];
        }
        __syncthreads();
#pragma unroll 1
        for (int icl = 0; icl < CH; icl++) {
            const float* p = &in_s[icl][row][cg * 4];
            float4 a0 = *(const float4*)p;        float2 b0 = *(const float2*)(p + 4);
            float4 a1 = *(const float4*)(p + 20); float2 b1 = *(const float2*)(p + 24);
            float4 a2 = *(const float4*)(p + 40); float2 b2 = *(const float2*)(p + 44);
            ull d0[6] = {pack2(a0.x), pack2(a0.y), pack2(a0.z), pack2(a0.w), pack2(b0.x), pack2(b0.y)};
            ull d1[6] = {pack2(a1.x), pack2(a1.y), pack2(a1.z), pack2(a1.w), pack2(b1.x), pack2(b1.y)};
            ull d2[6] = {pack2(a2.x), pack2(a2.y), pack2(a2.z), pack2(a2.w), pack2(b2.x), pack2(b2.y)};
#pragma unroll
            for (int pr = 0; pr < 8; pr++) {
                int pg = ocg * 8 + pr;                      // oc pair (2pg, 2pg+1)
                const ull* wp = &w_s2[(icl * 32 + pg) * 10];
                ulonglong2 w01 = *(const ulonglong2*)(wp);
                ulonglong2 w23 = *(const ulonglong2*)(wp + 2);
                ulonglong2 w45 = *(const ulonglong2*)(wp + 4);
                ulonglong2 w67 = *(const ulonglong2*)(wp + 6);
                ull w8 = wp[8];
#pragma unroll
                for (int px = 0; px < 4; px++) {
                    ull t = mul2(d0[px], w01.x);
                    fma2(t, d0[px + 1], w01.y);
                    fma2(t, d0[px + 2], w23.x);
                    fma2(t, d1[px],     w23.y);
                    fma2(t, d1[px + 1], w45.x);
                    fma2(t, d1[px + 2], w45.y);
                    fma2(t, d2[px],     w67.x);
                    fma2(t, d2[px + 1], w67.y);
                    fma2(t, d2[px + 2], w8);
                    acc[px][pr] = add2(acc[px][pr], t);
                }
            }
        }
        __syncthreads();
    }

    // epilogue 1: unpack, ReLU + store
    float pr[4][16];
    size_t pbase = (size_t)b * NF * HW + (size_t)(y0 + row) * IMG + (x0 + cg * 4);
#pragma unroll
    for (int pp = 0; pp < 8; pp++) {
#pragma unroll
        for (int px = 0; px < 4; px++) {
            float2 u = unpack2(acc[px][pp]);
            pr[px][2 * pp]     = fmaxf(u.x, 0.f);
            pr[px][2 * pp + 1] = fmaxf(u.y, 0.f);
        }
    }
#pragma unroll
    for (int j = 0; j < 16; j++) {
        int oc = ocg * 16 + j;
        *(float4*)(out + pbase + (size_t)oc * HW) =
            make_float4(pr[0][j], pr[1][j], pr[2][j], pr[3][j]);
    }

    // epilogue 2: per-block stats partial (identical tree to R10), NO atomics
    int tx = tid & 15, ty = tid >> 4;
    int lane = tid & 31, wid8 = tid >> 5;
    for (int oc = 0; oc < NF; oc++) {
        int og = oc >> 4, j = oc & 15;
        __syncthreads();
        if (ocg == og) {
#pragma unroll
            for (int px = 0; px < 4; px++) val_s[row][cg * 4 + px] = pr[px][j];
        }
        __syncthreads();
        float v = val_s[ty][tx];
        float s = v, q = v * v;
#pragma unroll
        for (int off = 16; off; off >>= 1) {
            s += __shfl_down_sync(0xffffffffu, s, off);
            q += __shfl_down_sync(0xffffffffu, q, off);
        }
        if (lane == 0) { red_s[0][oc][wid8] = s; red_s[1][oc][wid8] = q; }
    }
    __syncthreads();
    if (tid < 128) {
        int oc = tid & 63, which = tid >> 6;
        float t = 0.f;
#pragma unroll
        for (int wd = 0; wd < 8; wd++) t += red_s[which][oc][wd];
        g_part[(oc * 2 + which) * 2048 + bid] = t;          // deterministic store
    }
}

// ---------------- BN finalize: deterministic SEQUENTIAL sum over 2048 partials -----
// One thread per (channel, stat): fixed-order serial fp32 chain, structurally the
// same family as the (passing) atomic-sequential runs, but bit-reproducible.
__global__ __launch_bounds__(128) void bn_finalize_k(const float* __restrict__ gam,
                                                     const float* __restrict__ bet, int l) {
    __shared__ float sum_s[NF], sq_s[NF];
    int tid = threadIdx.x;
    int oc = tid & 63, which = tid >> 6;
    const float* p = &g_part[(oc * 2 + which) * 2048];
    float t = 0.f;
    for (int bid = 0; bid < 2048; bid++) t += p[bid];
    if (which == 0) sum_s[oc] = t; else sq_s[oc] = t;
    __syncthreads();
    if (tid < NF) {
        int c = tid;
        const float n = (float)((size_t)NB * HW);
        float mean = sum_s[c] / n;
        float var = sq_s[c] / n - mean * mean;
        float rs = rsqrtf(var + 1e-5f);
        float scl = gam[c] * rs;
        g_scale[l * NF + c] = scl;
        g_shift[l * NF + c] = bet[c] - mean * scl;
    }
}

// ---------------- final conv (R1/R9 source, verbatim) ------------------------------
__global__ __launch_bounds__(256) void conv_final_k(const float* __restrict__ w, float* __restrict__ outp) {
    __shared__ float in_s[CH][18][18];
    __shared__ __align__(16) float w_s[NF * 12];
    int tx = threadIdx.x & 15, ty = threadIdx.x >> 4;
    int x0 = blockIdx.x * 16, y0 = blockIdx.y * 16, b = blockIdx.z;
    const float* inb = g_h1 + (size_t)b * NF * HW;
    const float* sc = &g_scale[(NL - 1) * NF];
    const float* sh = &g_shift[(NL - 1) * NF];
    for (int i = threadIdx.x; i < NF * 9; i += 256)
        w_s[(i / 9) * 12 + (i % 9)] = w[i];
    float acc = 0.f;
    for (int c0 = 0; c0 < NF; c0 += CH) {
        for (int i = threadIdx.x; i < CH * 324; i += 256) {
            int c = i / 324, r = i % 324, yy = r / 18, xx = r % 18;
            int gy = y0 + yy - 1, gx = x0 + xx - 1;
            float v = 0.f;
            if (gy >= 0 && gy < 256 && gx >= 0 && gx < 256) {
                v = inb[(size_t)(c0 + c) * HW + (size_t)gy * IMG + gx];
                v = fmaxf(v * sc[c0 + c] + sh[c0 + c], 0.f);
            }
            in_s[c][yy][xx] = v;
        }
        __syncthreads();
#pragma unroll
        for (int icl = 0; icl < CH; icl++) {
            float i00 = in_s[icl][ty][tx],     i01 = in_s[icl][ty][tx + 1],     i02 = in_s[icl][ty][tx + 2];
            float i10 = in_s[icl][ty + 1][tx], i11 = in_s[icl][ty + 1][tx + 1], i12 = in_s[icl][ty + 1][tx + 2];
            float i20 = in_s[icl][ty + 2][tx], i21 = in_s[icl][ty + 2][tx + 1], i22 = in_s[icl][ty + 2][tx + 2];
            float4 wa = *(const float4*)&w_s[(c0 + icl) * 12];
            float4 wb = *(const float4*)&w_s[(c0 + icl) * 12 + 4];
            float  wc = w_s[(c0 + icl) * 12 + 8];
            acc += i00 * wa.x + i01 * wa.y + i02 * wa.z + i10 * wa.w +
                   i11 * wb.x + i12 * wb.y + i20 * wb.z + i21 * wb.w + i22 * wc;
        }
        __syncthreads();
    }
    size_t o = (size_t)b * HW + (size_t)(y0 + ty) * IMG + (x0 + tx);
    outp[o] = g_xpre[o] - acc;
}

// ---------------- launch ----------------------------------------------------------
extern "C" void kernel_launch(void* const* d_in, const int* in_sizes, int n_in,
                              void* d_out, int out_size) {
    const float* x       = (const float*)d_in[0];
    const float* w_init  = (const float*)d_in[1];
    const float* w_body  = (const float*)d_in[2];
    const float* bn_g    = (const float*)d_in[3];
    const float* bn_b    = (const float*)d_in[4];
    const float* w_final = (const float*)d_in[5];
    float* out = (float*)d_out;

    dim3 grid(16, 16, NB), blk(256);
    wprep_k<<<(NL * 8 * CH * 32 * 10 + 255) / 256, 256>>>(w_body);
    preprocess_k<<<grid, blk>>>(x);
    conv_init_k<<<grid, blk>>>(w_init);
    for (int l = 0; l < NL; l++) {
        conv_body_k<<<grid, blk>>>(l);
        bn_finalize_k<<<1, 128>>>(bn_g + l * NF, bn_b + l * NF, l);
    }
    conv_final_k<<<grid, blk>>>(w_final, out);
}

// round 15
// speedup vs baseline: 1.0587x; 1.0556x over previous
#include <cuda_runtime.h>
#include <cstdint>
#include <cstddef>

#define IMG 256
#define HW  65536
#define NF  64
#define NB  8
#define NL  15
#define CH  8

typedef unsigned long long ull;

// ---------------- scratch (device globals; no allocation allowed) ----------------
__device__ float g_xpre[(size_t)NB * HW];                  // 2 MB
__device__ float g_h0[(size_t)NB * NF * HW];               // 128 MB
__device__ float g_h1[(size_t)NB * NF * HW];               // 128 MB
__device__ float g_part[NF * 2 * 2048];                    // per-block stats partials, 1 MB
__device__ float g_scale[NL * NF];
__device__ float g_shift[NL * NF];
// weights pre-paired: g_wp[(((l*8+chunk)*CH+icl)*32+pg)*10+k] = (w[oc=2pg], w[oc=2pg+1]) at tap k
__device__ ull   g_wp[(size_t)NL * 8 * CH * 32 * 10];      // ~2.46 MB

// ---------------- f32x2 helpers (per-lane exact IEEE fp32) -------------------------
__device__ __forceinline__ ull pack2(float v) {
    ull r; asm("mov.b64 %0, {%1, %1};" : "=l"(r) : "f"(v)); return r;
}
__device__ __forceinline__ ull mul2(ull a, ull b) {
    ull d; asm("mul.rn.f32x2 %0, %1, %2;" : "=l"(d) : "l"(a), "l"(b)); return d;
}
__device__ __forceinline__ void fma2(ull& d, ull a, ull b) {
    asm("fma.rn.f32x2 %0, %1, %2, %0;" : "+l"(d) : "l"(a), "l"(b));
}
__device__ __forceinline__ ull add2(ull a, ull b) {
    ull d; asm("add.rn.f32x2 %0, %1, %2;" : "=l"(d) : "l"(a), "l"(b)); return d;
}
__device__ __forceinline__ float2 unpack2(ull v) {
    float2 r; asm("mov.b64 {%0, %1}, %2;" : "=f"(r.x), "=f"(r.y) : "l"(v)); return r;
}

// ---------------- weight pre-pairing ------------------------------------------------
__global__ void wprep_k(const float* __restrict__ w) {
    int i = blockIdx.x * blockDim.x + threadIdx.x;
    if (i >= NL * 8 * CH * 32 * 10) return;
    int k   = i % 10;
    int r   = i / 10;
    int pg  = r % 32;
    int r2  = r / 32;
    int icl = r2 % CH;
    int r3  = r2 / CH;
    int chunk = r3 % 8;
    int l     = r3 / 8;
    int ic = chunk * CH + icl;
    unsigned lo = 0, hi = 0;
    if (k < 9) {
        lo = __float_as_uint(w[(((size_t)l * NF + 2 * pg)     * NF + ic) * 9 + k]);
        hi = __float_as_uint(w[(((size_t)l * NF + 2 * pg + 1) * NF + ic) * 9 + k]);
    }
    g_wp[i] = ((ull)hi << 32) | (ull)lo;
}

// ---------------- preprocessing (R1/R9 source, verbatim) ---------------------------
__global__ __launch_bounds__(256) void preprocess_k(const float* __restrict__ x) {
    __shared__ float t[20][20];
    int tx = threadIdx.x & 15, ty = threadIdx.x >> 4;
    int x0 = blockIdx.x * 16, y0 = blockIdx.y * 16, b = blockIdx.z;
    const float* xb = x + (size_t)b * HW;
    for (int i = threadIdx.x; i < 400; i += 256) {
        int yy = i / 20, xx = i % 20;
        int gy = y0 + yy - 2, gx = x0 + xx - 2;
        if (gy < 0) gy = -gy;
        if (gy > 255) gy = 510 - gy;
        if (gx < 0) gx = -gx;
        if (gx > 255) gx = 510 - gx;
        float v = xb[gy * IMG + gx];
        float xn = (v + 1.f) * 0.5f;
        xn = fminf(fmaxf(xn, 1e-6f), 1.f);
        t[yy][xx] = 0.6f * xn + 0.4f * xn * sqrtf(xn);
    }
    __syncthreads();
    float c = t[ty + 2][tx + 2];
    float num = 0.f, den = 0.f;
#pragma unroll
    for (int dy = -2; dy <= 2; dy++)
#pragma unroll
        for (int dx = -2; dx <= 2; dx++) {
            float nb = t[ty + 2 + dy][tx + 2 + dx];
            float d = nb - c;
            float w = expf(-(float)(dy * dy + dx * dx) * 2.0e-4f - d * d * 200.f);
            num += w * nb;
            den += w;
        }
    g_xpre[(size_t)b * HW + (size_t)(y0 + ty) * IMG + (x0 + tx)] = num / den;
}

// ---------------- init conv (R1/R9 source, verbatim) -------------------------------
__global__ __launch_bounds__(256) void conv_init_k(const float* __restrict__ w) {
    __shared__ float in_s[18][18];
    __shared__ __align__(16) float w_s[NF * 12];
    int tx = threadIdx.x & 15, ty = threadIdx.x >> 4;
    int x0 = blockIdx.x * 16, y0 = blockIdx.y * 16, b = blockIdx.z;
    for (int i = threadIdx.x; i < 324; i += 256) {
        int yy = i / 18, xx = i % 18;
        int gy = y0 + yy - 1, gx = x0 + xx - 1;
        float v = 0.f;
        if (gy >= 0 && gy < 256 && gx >= 0 && gx < 256)
            v = g_xpre[(size_t)b * HW + (size_t)gy * IMG + gx];
        in_s[yy][xx] = v;
    }
    for (int i = threadIdx.x; i < NF * 9; i += 256)
        w_s[(i / 9) * 12 + (i % 9)] = w[i];
    __syncthreads();
    float i00 = in_s[ty][tx],     i01 = in_s[ty][tx + 1],     i02 = in_s[ty][tx + 2];
    float i10 = in_s[ty + 1][tx], i11 = in_s[ty + 1][tx + 1], i12 = in_s[ty + 1][tx + 2];
    float i20 = in_s[ty + 2][tx], i21 = in_s[ty + 2][tx + 1], i22 = in_s[ty + 2][tx + 2];
    float* outp = g_h0 + (size_t)b * NF * HW + (size_t)(y0 + ty) * IMG + (x0 + tx);
#pragma unroll
    for (int oc = 0; oc < NF; oc++) {
        float4 wa = *(const float4*)&w_s[oc * 12];
        float4 wb = *(const float4*)&w_s[oc * 12 + 4];
        float  wc = w_s[oc * 12 + 8];
        float a = i00 * wa.x + i01 * wa.y + i02 * wa.z + i10 * wa.w +
                  i11 * wb.x + i12 * wb.y + i20 * wb.z + i21 * wb.w + i22 * wc;
        outp[(size_t)oc * HW] = fmaxf(a, 0.f);
    }
}

// ---------------- body conv: f32x2, double-buffered input staging ------------------
// Numerics are bit-identical to R14: same FP ops, same order; only scheduling moved.
__global__ __launch_bounds__(256) void conv_body_k(int l) {
    __shared__ float in_s[2][CH][18][20];                  // 23040 B, double buffer
    __shared__ __align__(16) ull w_s2[CH * 32 * 10];       // 20480 B
    __shared__ float red_s[2][NF][8];                      // 4096 B

    const float* in  = (l & 1) ? g_h1 : g_h0;
    float*       out = (l & 1) ? g_h0 : g_h1;
    const float* sc = (l > 0) ? &g_scale[(l - 1) * NF] : nullptr;
    const float* sh = (l > 0) ? &g_shift[(l - 1) * NF] : nullptr;

    int tid = threadIdx.x;
    int ocg = tid >> 6, pid = tid & 63;
    int row = pid >> 2, cg = pid & 3;
    int x0 = blockIdx.x * 16, y0 = blockIdx.y * 16, b = blockIdx.z;
    int bid = (b * 16 + blockIdx.y) * 16 + blockIdx.x;     // 0..2047, fixed mapping
    const float* inb = in + (size_t)b * NF * HW;

    ull acc[4][8];
#pragma unroll
    for (int px = 0; px < 4; px++)
#pragma unroll
        for (int p = 0; p < 8; p++) acc[px][p] = 0ull;

    // ---- staging lambdas (identical value computation to R14) ----
    auto stage_in = [&](int chunk, int buf) {
        int c0 = chunk * CH;
        for (int i = tid; i < CH * 324; i += 256) {
            int c = i / 324, r2 = i % 324, yy = r2 / 18, xx = r2 % 18;
            int gy = y0 + yy - 1, gx = x0 + xx - 1;
            float v = 0.f;
            if (gy >= 0 && gy < 256 && gx >= 0 && gx < 256) {
                v = inb[(size_t)(c0 + c) * HW + (size_t)gy * IMG + gx];
                if (sc) v = fmaxf(v * sc[c0 + c] + sh[c0 + c], 0.f);
            }
            in_s[buf][c][yy][xx] = v;
        }
    };
    auto stage_w = [&](int chunk) {
        const ull* src = g_wp + ((size_t)l * 8 + chunk) * (CH * 32 * 10);
        for (int i = tid; i < CH * 32 * 10; i += 256) w_s2[i] = src[i];
    };

    // prologue: chunk 0 into buffer 0
    stage_in(0, 0);
    stage_w(0);
    __syncthreads();

    for (int cc = 0; cc < 8; cc++) {
        int buf = cc & 1;
        if (cc < 7) stage_in(cc + 1, buf ^ 1);             // hidden behind compute
#pragma unroll 1
        for (int icl = 0; icl < CH; icl++) {
            const float* p = &in_s[buf][icl][row][cg * 4];
            float4 a0 = *(const float4*)p;        float2 b0 = *(const float2*)(p + 4);
            float4 a1 = *(const float4*)(p + 20); float2 b1 = *(const float2*)(p + 24);
            float4 a2 = *(const float4*)(p + 40); float2 b2 = *(const float2*)(p + 44);
            ull d0[6] = {pack2(a0.x), pack2(a0.y), pack2(a0.z), pack2(a0.w), pack2(b0.x), pack2(b0.y)};
            ull d1[6] = {pack2(a1.x), pack2(a1.y), pack2(a1.z), pack2(a1.w), pack2(b1.x), pack2(b1.y)};
            ull d2[6] = {pack2(a2.x), pack2(a2.y), pack2(a2.z), pack2(a2.w), pack2(b2.x), pack2(b2.y)};
#pragma unroll
            for (int pr = 0; pr < 8; pr++) {
                int pg = ocg * 8 + pr;                      // oc pair (2pg, 2pg+1)
                const ull* wp = &w_s2[(icl * 32 + pg) * 10];
                ulonglong2 w01 = *(const ulonglong2*)(wp);
                ulonglong2 w23 = *(const ulonglong2*)(wp + 2);
                ulonglong2 w45 = *(const ulonglong2*)(wp + 4);
                ulonglong2 w67 = *(const ulonglong2*)(wp + 6);
                ull w8 = wp[8];
#pragma unroll
                for (int px = 0; px < 4; px++) {
                    ull t = mul2(d0[px], w01.x);
                    fma2(t, d0[px + 1], w01.y);
                    fma2(t, d0[px + 2], w23.x);
                    fma2(t, d1[px],     w23.y);
                    fma2(t, d1[px + 1], w45.x);
                    fma2(t, d1[px + 2], w45.y);
                    fma2(t, d2[px],     w67.x);
                    fma2(t, d2[px + 1], w67.y);
                    fma2(t, d2[px + 2], w8);
                    acc[px][pr] = add2(acc[px][pr], t);
                }
            }
        }
        __syncthreads();                                   // compute done, next input staged
        if (cc < 7) {
            stage_w(cc + 1);                               // w_s2 reuse, needs barrier above
            __syncthreads();
        }
    }

    // epilogue 1: unpack, ReLU + store (values identical to R14)
    float pr[4][16];
    size_t pbase = (size_t)b * NF * HW + (size_t)(y0 + row) * IMG + (x0 + cg * 4);
#pragma unroll
    for (int pp = 0; pp < 8; pp++) {
#pragma unroll
        for (int px = 0; px < 4; px++) {
            float2 u = unpack2(acc[px][pp]);
            pr[px][2 * pp]     = fmaxf(u.x, 0.f);
            pr[px][2 * pp + 1] = fmaxf(u.y, 0.f);
        }
    }
#pragma unroll
    for (int j = 0; j < 16; j++) {
        int oc = ocg * 16 + j;
        *(float4*)(out + pbase + (size_t)oc * HW) =
            make_float4(pr[0][j], pr[1][j], pr[2][j], pr[3][j]);
    }

    // epilogue 2: stats, 8 ocs per barrier pair; per-oc tree order IDENTICAL to R14.
    // val buffers alias in_s (dead after main loop; first sync below orders reuse).
    float* val4 = (float*)in_s;                            // 8 bufs x 256 floats = 8 KB
    int tx = tid & 15, ty = tid >> 4;
    int lane = tid & 31, wid8 = tid >> 5;
    for (int ocq = 0; ocq < 8; ocq++) {
        int og = ocq >> 1, j0 = (ocq & 1) * 8;
        __syncthreads();
        if (ocg == og) {
#pragma unroll
            for (int k = 0; k < 8; k++)
#pragma unroll
                for (int px = 0; px < 4; px++)
                    val4[k * 256 + row * 16 + cg * 4 + px] = pr[px][j0 + k];
        }
        __syncthreads();
#pragma unroll
        for (int k = 0; k < 8; k++) {
            int oc = ocq * 8 + k;
            float v = val4[k * 256 + ty * 16 + tx];
            float s = v, q = v * v;
#pragma unroll
            for (int off = 16; off; off >>= 1) {
                s += __shfl_down_sync(0xffffffffu, s, off);
                q += __shfl_down_sync(0xffffffffu, q, off);
            }
            if (lane == 0) { red_s[0][oc][wid8] = s; red_s[1][oc][wid8] = q; }
        }
    }
    __syncthreads();
    if (tid < 128) {
        int oc = tid & 63, which = tid >> 6;
        float t = 0.f;
#pragma unroll
        for (int wd = 0; wd < 8; wd++) t += red_s[which][oc][wd];
        g_part[(oc * 2 + which) * 2048 + bid] = t;         // deterministic store
    }
}

// ---------------- BN finalize (R14 source, verbatim — sequential, deterministic) ---
__global__ __launch_bounds__(128) void bn_finalize_k(const float* __restrict__ gam,
                                                     const float* __restrict__ bet, int l) {
    __shared__ float sum_s[NF], sq_s[NF];
    int tid = threadIdx.x;
    int oc = tid & 63, which = tid >> 6;
    const float* p = &g_part[(oc * 2 + which) * 2048];
    float t = 0.f;
    for (int bid = 0; bid < 2048; bid++) t += p[bid];
    if (which == 0) sum_s[oc] = t; else sq_s[oc] = t;
    __syncthreads();
    if (tid < NF) {
        int c = tid;
        const float n = (float)((size_t)NB * HW);
        float mean = sum_s[c] / n;
        float var = sq_s[c] / n - mean * mean;
        float rs = rsqrtf(var + 1e-5f);
        float scl = gam[c] * rs;
        g_scale[l * NF + c] = scl;
        g_shift[l * NF + c] = bet[c] - mean * scl;
    }
}

// ---------------- final conv (R1/R9 source, verbatim) ------------------------------
__global__ __launch_bounds__(256) void conv_final_k(const float* __restrict__ w, float* __restrict__ outp) {
    __shared__ float in_s[CH][18][18];
    __shared__ __align__(16) float w_s[NF * 12];
    int tx = threadIdx.x & 15, ty = threadIdx.x >> 4;
    int x0 = blockIdx.x * 16, y0 = blockIdx.y * 16, b = blockIdx.z;
    const float* inb = g_h1 + (size_t)b * NF * HW;
    const float* sc = &g_scale[(NL - 1) * NF];
    const float* sh = &g_shift[(NL - 1) * NF];
    for (int i = threadIdx.x; i < NF * 9; i += 256)
        w_s[(i / 9) * 12 + (i % 9)] = w[i];
    float acc = 0.f;
    for (int c0 = 0; c0 < NF; c0 += CH) {
        for (int i = threadIdx.x; i < CH * 324; i += 256) {
            int c = i / 324, r = i % 324, yy = r / 18, xx = r % 18;
            int gy = y0 + yy - 1, gx = x0 + xx - 1;
            float v = 0.f;
            if (gy >= 0 && gy < 256 && gx >= 0 && gx < 256) {
                v = inb[(size_t)(c0 + c) * HW + (size_t)gy * IMG + gx];
                v = fmaxf(v * sc[c0 + c] + sh[c0 + c], 0.f);
            }
            in_s[c][yy][xx] = v;
        }
        __syncthreads();
#pragma unroll
        for (int icl = 0; icl < CH; icl++) {
            float i00 = in_s[icl][ty][tx],     i01 = in_s[icl][ty][tx + 1],     i02 = in_s[icl][ty][tx + 2];
            float i10 = in_s[icl][ty + 1][tx], i11 = in_s[icl][ty + 1][tx + 1], i12 = in_s[icl][ty + 1][tx + 2];
            float i20 = in_s[icl][ty + 2][tx], i21 = in_s[icl][ty + 2][tx + 1], i22 = in_s[icl][ty + 2][tx + 2];
            float4 wa = *(const float4*)&w_s[(c0 + icl) * 12];
            float4 wb = *(const float4*)&w_s[(c0 + icl) * 12 + 4];
            float  wc = w_s[(c0 + icl) * 12 + 8];
            acc += i00 * wa.x + i01 * wa.y + i02 * wa.z + i10 * wa.w +
                   i11 * wb.x + i12 * wb.y + i20 * wb.z + i21 * wb.w + i22 * wc;
        }
        __syncthreads();
    }
    size_t o = (size_t)b * HW + (size_t)(y0 + ty) * IMG + (x0 + tx);
    outp[o] = g_xpre[o] - acc;
}

// ---------------- launch ----------------------------------------------------------
extern "C" void kernel_launch(void* const* d_in, const int* in_sizes, int n_in,
                              void* d_out, int out_size) {
    const float* x       = (const float*)d_in[0];
    const float* w_init  = (const float*)d_in[1];
    const float* w_body  = (const float*)d_in[2];
    const float* bn_g    = (const float*)d_in[3];
    const float* bn_b    = (const float*)d_in[4];
    const float* w_final = (const float*)d_in[5];
    float* out = (float*)d_out;

    dim3 grid(16, 16, NB), blk(256);
    wprep_k<<<(NL * 8 * CH * 32 * 10 + 255) / 256, 256>>>(w_body);
    preprocess_k<<<grid, blk>>>(x);
    conv_init_k<<<grid, blk>>>(w_init);
    for (int l = 0; l < NL; l++) {
        conv_body_k<<<grid, blk>>>(l);
        bn_finalize_k<<<1, 128>>>(bn_g + l * NF, bn_b + l * NF, l);
    }
    conv_final_k<<<grid, blk>>>(w_final, out);
}